// round 1
// baseline (speedup 1.0000x reference)
#include <cuda_runtime.h>
#include <cstdint>
#include <cstdio>
#include <math.h>

#define E_BONDS   131072
#define N_ATOMS_  65536
#define HID       256
#define MAXNB     6
#define AFD       143
#define KIN       157     // AFD + BOND_FDIM(14)
#define BMOL      2048
#define APM       32

// scratch: binput, message, agg (E*H each) + neia, atomh, tmp, tbuf (N*H each)
#define EH  ((size_t)E_BONDS * HID)
#define NH  ((size_t)N_ATOMS_ * HID)
__device__ float g_scratch[3 * (size_t)E_BONDS * HID + 4 * (size_t)N_ATOMS_ * HID];

// ---------------------------------------------------------------------------
// float4 helpers
// ---------------------------------------------------------------------------
__device__ __forceinline__ float4 f4add(float4 a, float4 b) {
    return make_float4(a.x + b.x, a.y + b.y, a.z + b.z, a.w + b.w);
}
__device__ __forceinline__ float4 f4fma(float s, float4 a, float4 acc) {
    acc.x += s * a.x; acc.y += s * a.y; acc.z += s * a.z; acc.w += s * a.w;
    return acc;
}
__device__ __forceinline__ float f4dot(float4 a, float4 b) {
    return a.x * b.x + a.y * b.y + a.z * b.z + a.w * b.w;
}

// ---------------------------------------------------------------------------
// SGEMM: C[M,256] = A[M,K] @ B[K,256] (+ D) (+ bias) (relu)
// Tile 64x256, BK=8, 256 threads, 8x8 per thread. N fixed to 256.
// ---------------------------------------------------------------------------
template<bool HAS_D, bool HAS_BIAS, bool RELU, bool HAS_RAW>
__global__ void __launch_bounds__(256, 2) sgemm64x256(
    int M, int K,
    const float* __restrict__ A, int lda,
    const float* __restrict__ B,          // [K,256] row-major
    const float* __restrict__ D,          // [M,256] elementwise add (optional)
    const float* __restrict__ bias,       // [256] (optional)
    float* __restrict__ out,
    float* __restrict__ raw)              // pre-relu copy (optional)
{
    __shared__ float As[8][64];
    __shared__ float Bs[8][256];

    const int tid = threadIdx.x;
    const int m0  = blockIdx.x * 64;
    const int ty  = tid >> 5;        // 0..7  -> rows ty*8..+7
    const int tx  = tid & 31;        // 0..31 -> cols tx*8..+7

    // loader indices
    const int a_m = tid >> 2;            // 0..63
    const int a_k = (tid & 3) * 2;       // 0,2,4,6
    const int b_k = tid >> 5;            // 0..7
    const int b_n = (tid & 31) * 8;      // 0..248

    float acc[8][8];
#pragma unroll
    for (int i = 0; i < 8; i++)
#pragma unroll
        for (int j = 0; j < 8; j++) acc[i][j] = 0.f;

    for (int k0 = 0; k0 < K; k0 += 8) {
        // load A tile (scalar, guarded for ragged K / odd lda)
#pragma unroll
        for (int i = 0; i < 2; i++) {
            int kk = k0 + a_k + i;
            As[a_k + i][a_m] = (kk < K) ? A[(size_t)(m0 + a_m) * lda + kk] : 0.f;
        }
        // load B tile (vectorized, ldb == 256)
        if (k0 + b_k < K) {
            const float4* bp = (const float4*)&B[(size_t)(k0 + b_k) * 256 + b_n];
            *(float4*)&Bs[b_k][b_n]     = bp[0];
            *(float4*)&Bs[b_k][b_n + 4] = bp[1];
        } else {
            float4 z = make_float4(0, 0, 0, 0);
            *(float4*)&Bs[b_k][b_n] = z;
            *(float4*)&Bs[b_k][b_n + 4] = z;
        }
        __syncthreads();

#pragma unroll
        for (int k = 0; k < 8; k++) {
            float4 a0 = *(float4*)&As[k][ty * 8];
            float4 a1 = *(float4*)&As[k][ty * 8 + 4];
            float4 b0 = *(float4*)&Bs[k][tx * 8];
            float4 b1 = *(float4*)&Bs[k][tx * 8 + 4];
            float av[8] = {a0.x, a0.y, a0.z, a0.w, a1.x, a1.y, a1.z, a1.w};
            float bv[8] = {b0.x, b0.y, b0.z, b0.w, b1.x, b1.y, b1.z, b1.w};
#pragma unroll
            for (int i = 0; i < 8; i++)
#pragma unroll
                for (int j = 0; j < 8; j++) acc[i][j] += av[i] * bv[j];
        }
        __syncthreads();
    }

    // epilogue
#pragma unroll
    for (int i = 0; i < 8; i++) {
        const size_t m = (size_t)(m0 + ty * 8 + i);
#pragma unroll
        for (int jj = 0; jj < 2; jj++) {
            const int n = tx * 8 + jj * 4;
            float4 v = make_float4(acc[i][jj * 4 + 0], acc[i][jj * 4 + 1],
                                   acc[i][jj * 4 + 2], acc[i][jj * 4 + 3]);
            if (HAS_D)    v = f4add(v, *(const float4*)&D[m * 256 + n]);
            if (HAS_BIAS) v = f4add(v, *(const float4*)&bias[n]);
            if (HAS_RAW)  *(float4*)&raw[m * 256 + n] = v;
            if (RELU) {
                v.x = fmaxf(v.x, 0.f); v.y = fmaxf(v.y, 0.f);
                v.z = fmaxf(v.z, 0.f); v.w = fmaxf(v.w, 0.f);
            }
            *(float4*)&out[m * 256 + n] = v;
        }
    }
}

// ---------------------------------------------------------------------------
// Bond attention gather: one warp per bond.
// agg[e] = sum_j softmax_j(msg[bgraph[e,j]] . Wma1) * msg[bgraph[e,j]]
// ---------------------------------------------------------------------------
__global__ void __launch_bounds__(256) bond_attn(
    const float* __restrict__ msg, const int* __restrict__ bgraph,
    const float* __restrict__ wma, float* __restrict__ agg)
{
    const int gw   = (blockIdx.x * 256 + threadIdx.x) >> 5;
    const int lane = threadIdx.x & 31;
    if (gw >= E_BONDS) return;

    const float4 w0 = *(const float4*)&wma[lane * 8];
    const float4 w1 = *(const float4*)&wma[lane * 8 + 4];

    float4 r0[6], r1[6];
    float  s[6];
#pragma unroll
    for (int j = 0; j < 6; j++) {
        const int nb = bgraph[gw * 6 + j];
        const float4* p = (const float4*)(msg + (size_t)nb * 256) + lane * 2;
        r0[j] = p[0]; r1[j] = p[1];
        float d = f4dot(r0[j], w0) + f4dot(r1[j], w1);
#pragma unroll
        for (int o = 16; o > 0; o >>= 1) d += __shfl_xor_sync(0xffffffffu, d, o);
        s[j] = d;
    }
    float mx = s[0];
#pragma unroll
    for (int j = 1; j < 6; j++) mx = fmaxf(mx, s[j]);
    float e[6], sum = 0.f;
#pragma unroll
    for (int j = 0; j < 6; j++) { e[j] = expf(s[j] - mx); sum += e[j]; }
    const float inv = 1.0f / sum;

    float4 a0 = make_float4(0, 0, 0, 0), a1 = make_float4(0, 0, 0, 0);
#pragma unroll
    for (int j = 0; j < 6; j++) {
        const float w = e[j] * inv;
        a0 = f4fma(w, r0[j], a0);
        a1 = f4fma(w, r1[j], a1);
    }
    float4* o = (float4*)(agg + (size_t)gw * 256) + lane * 2;
    o[0] = a0; o[1] = a1;
}

// ---------------------------------------------------------------------------
// Atom gather: one warp per atom, nei_a[n] = sum_j msg[agraph[n,j]]
// ---------------------------------------------------------------------------
__global__ void __launch_bounds__(256) atom_gather(
    const float* __restrict__ msg, const int* __restrict__ agraph,
    float* __restrict__ neia)
{
    const int ga   = (blockIdx.x * 256 + threadIdx.x) >> 5;
    const int lane = threadIdx.x & 31;
    if (ga >= N_ATOMS_) return;

    float4 a0 = make_float4(0, 0, 0, 0), a1 = make_float4(0, 0, 0, 0);
#pragma unroll
    for (int j = 0; j < 6; j++) {
        const int nb = agraph[ga * 6 + j];
        const float4* p = (const float4*)(msg + (size_t)nb * 256) + lane * 2;
        a0 = f4add(a0, p[0]);
        a1 = f4add(a1, p[1]);
    }
    float4* o = (float4*)(neia + (size_t)ga * 256) + lane * 2;
    o[0] = a0; o[1] = a1;
}

// ---------------------------------------------------------------------------
// Per-molecule self-attention: scores = (hW) h^T, softmax rows, t = att @ h
// block = one molecule (32 atoms x 256), 256 threads, padded smem
// ---------------------------------------------------------------------------
#define PAD 257
#define MOLATTN_SMEM ((2 * 32 * PAD + 32 * 32) * (int)sizeof(float))

__global__ void __launch_bounds__(256) mol_attn(
    const float* __restrict__ atomh, const float* __restrict__ hW,
    float* __restrict__ t)
{
    extern __shared__ float sm[];
    float* sh = sm;                 // [32][PAD]  h
    float* sw = sm + 32 * PAD;      // [32][PAD]  hW
    float* sa = sm + 2 * 32 * PAD;  // [32][32]   scores / att

    const int b = blockIdx.x, tid = threadIdx.x;
    const float* hb = atomh + (size_t)b * 32 * 256;
    const float* wb = hW    + (size_t)b * 32 * 256;

    for (int i = tid; i < 32 * 256; i += 256) {
        const int a = i >> 8, k = i & 255;
        sh[a * PAD + k] = hb[i];
        sw[a * PAD + k] = wb[i];
    }
    __syncthreads();

    // scores[a][c] = sw[a] . sh[c]
    for (int p = tid; p < 1024; p += 256) {
        const int a = p >> 5, c = p & 31;
        float s = 0.f;
#pragma unroll 8
        for (int k = 0; k < 256; k++) s += sw[a * PAD + k] * sh[c * PAD + k];
        sa[a * 32 + c] = s;
    }
    __syncthreads();

    // row softmax (warp per row)
    const int wid = tid >> 5, lane = tid & 31;
    for (int a = wid; a < 32; a += 8) {
        float v = sa[a * 32 + lane];
        float m = v;
#pragma unroll
        for (int o = 16; o > 0; o >>= 1) m = fmaxf(m, __shfl_xor_sync(0xffffffffu, m, o));
        float ev = expf(v - m);
        float sum = ev;
#pragma unroll
        for (int o = 16; o > 0; o >>= 1) sum += __shfl_xor_sync(0xffffffffu, sum, o);
        sa[a * 32 + lane] = ev / sum;
    }
    __syncthreads();

    // t[a][k] = sum_c att[a][c] * h[c][k]; thread = one column k
    const int k = tid;
    float acc[32];
#pragma unroll
    for (int a = 0; a < 32; a++) acc[a] = 0.f;
    for (int c = 0; c < 32; c++) {
        const float hv = sh[c * PAD + k];
#pragma unroll
        for (int a = 0; a < 32; a++) acc[a] += sa[a * 32 + c] * hv;
    }
#pragma unroll
    for (int a = 0; a < 32; a++)
        t[((size_t)b * 32 + a) * 256 + k] = acc[a];
}

// ---------------------------------------------------------------------------
// Final: mol_vecs[b][k] = sum_a (atom_h + att_h) / 32
// ---------------------------------------------------------------------------
__global__ void __launch_bounds__(256) mol_reduce(
    const float* __restrict__ atomh, const float* __restrict__ atth,
    float* __restrict__ out)
{
    const int b = blockIdx.x, k = threadIdx.x;
    const float* ph = atomh + (size_t)b * 32 * 256 + k;
    const float* pa = atth  + (size_t)b * 32 * 256 + k;
    float s = 0.f;
#pragma unroll
    for (int a = 0; a < 32; a++) s += ph[a * 256] + pa[a * 256];
    out[(size_t)b * 256 + k] = s * (1.0f / 32.0f);
}

// ---------------------------------------------------------------------------
extern "C" void kernel_launch(void* const* d_in, const int* in_sizes, int n_in,
                              void* d_out, int out_size)
{
    const float* fatoms = (const float*)d_in[0];
    const float* fbonds = (const float*)d_in[1];
    const int*   agraph = (const int*)d_in[2];
    const int*   bgraph = (const int*)d_in[3];
    // d_in[4] = atoms_per_mol (scalar, fixed 32)
    const float* W_i    = (const float*)d_in[5];
    const float* W_h    = (const float*)d_in[6];
    const float* W_o_w  = (const float*)d_in[7];
    const float* W_o_b  = (const float*)d_in[8];
    const float* W_a    = (const float*)d_in[9];
    const float* W_b_w  = (const float*)d_in[10];
    const float* W_b_b  = (const float*)d_in[11];
    const float* W_ma1  = (const float*)d_in[12];
    float* out = (float*)d_out;

    float* scratch = nullptr;
    cudaGetSymbolAddress((void**)&scratch, g_scratch);
    float* binput  = scratch;
    float* message = binput  + EH;
    float* agg     = message + EH;
    float* neia    = agg     + EH;
    float* atomh   = neia    + NH;
    float* tmp     = atomh   + NH;   // atomtmp -> hW -> att_h (sequential reuse)
    float* tbuf    = tmp     + NH;   // t = att_w @ h

    cudaFuncSetAttribute(mol_attn, cudaFuncAttributeMaxDynamicSharedMemorySize,
                         MOLATTN_SMEM);

    // G1: binput = fbonds @ W_i ; message = relu(binput)
    sgemm64x256<false, false, true, true><<<E_BONDS / 64, 256>>>(
        E_BONDS, KIN, fbonds, KIN, W_i, nullptr, nullptr, message, binput);

    // 3 message-passing iterations
    for (int it = 0; it < 3; it++) {
        bond_attn<<<E_BONDS / 8, 256>>>(message, bgraph, W_ma1, agg);
        sgemm64x256<true, false, true, false><<<E_BONDS / 64, 256>>>(
            E_BONDS, HID, agg, HID, W_h, binput, nullptr, message, nullptr);
    }

    // atom readout
    atom_gather<<<N_ATOMS_ / 8, 256>>>(message, agraph, neia);
    // atom_h = relu([fatoms, neia] @ W_o_w + b) in two passes
    sgemm64x256<false, false, false, false><<<N_ATOMS_ / 64, 256>>>(
        N_ATOMS_, AFD, fatoms, AFD, W_o_w, nullptr, nullptr, tmp, nullptr);
    sgemm64x256<true, true, true, false><<<N_ATOMS_ / 64, 256>>>(
        N_ATOMS_, HID, neia, HID, W_o_w + (size_t)AFD * HID, tmp, W_o_b, atomh, nullptr);

    // molecule self-attention pooling
    sgemm64x256<false, false, false, false><<<N_ATOMS_ / 64, 256>>>(
        N_ATOMS_, HID, atomh, HID, W_a, nullptr, nullptr, tmp, nullptr);   // hW
    mol_attn<<<BMOL, 256, MOLATTN_SMEM>>>(atomh, tmp, tbuf);               // t
    sgemm64x256<false, true, true, false><<<N_ATOMS_ / 64, 256>>>(
        N_ATOMS_, HID, tbuf, HID, W_b_w, nullptr, W_b_b, tmp, nullptr);    // att_h
    mol_reduce<<<BMOL, 256>>>(atomh, tmp, out);
}